// round 10
// baseline (speedup 1.0000x reference)
#include <cuda_runtime.h>
#include <cuda_fp16.h>

// Problem constants (fixed by the dataset)
static constexpr int NN = 50000;   // nodes
static constexpr int NE = 800000;  // edges
// features: 128 -> 128 (hidden) -> 64 (out)

// scan decomposition (CHUNK divisible by 4 for int4 loads)
static constexpr int SCAN_T = 1024;
static constexpr int CHUNK  = 52;          // 1024*52 = 53248 >= NN

// ---------------- scratch (__device__ globals; no allocs allowed) ------------
__device__ float  g_ax [(size_t)NN * 128]; // nin-scaled layer1 aggregate (GEMM input A)
__device__ __half g_y2h[(size_t)NN * 64];  // (relu(h1)*nout) @ W2, fp16
__device__ __half g_hx [(size_t)NN * 128]; // h * nout, fp16 (layer1 gather source)
__device__ int    g_odeg[NN];
__device__ int    g_ideg[NN];
__device__ float  g_nout[NN];
__device__ float  g_nin [NN];
__device__ int    g_off [NN + 1];          // CSR offsets (by dst)
__device__ int    g_cur [NN];              // scatter cursors
__device__ int    g_bucket[NE];            // src ids grouped by dst
__device__ int    g_part[SCAN_T];          // per-chunk partial sums

// ---------------- packed f32x2 helpers (PTX-only) -----------------------------
__device__ __forceinline__ void fma2(unsigned long long& d,
                                     unsigned long long a,
                                     unsigned long long b) {
    asm("fma.rn.f32x2 %0, %1, %2, %0;" : "+l"(d) : "l"(a), "l"(b));
}
__device__ __forceinline__ unsigned long long pack2(float x) {
    unsigned long long r;
    asm("mov.b64 %0, {%1, %1};" : "=l"(r) : "f"(x));
    return r;
}
__device__ __forceinline__ float2 unpk(unsigned long long v) {
    float lo, hi;
    asm("mov.b64 {%0, %1}, %2;" : "=f"(lo), "=f"(hi) : "l"(v));
    return make_float2(lo, hi);
}

// ---------------- graph preprocessing ----------------------------------------

__global__ void degree_k(const int* __restrict__ src, const int* __restrict__ dst) {
    int i0 = blockIdx.x * blockDim.x + threadIdx.x;
    int stride = gridDim.x * blockDim.x;
    for (int i = i0; i < NE; i += stride) {
        atomicAdd(&g_odeg[src[i]], 1);
        atomicAdd(&g_ideg[dst[i]], 1);
    }
}

// norms (grid-stride) + per-chunk partial degree sums (first SCAN_T threads)
__global__ void norm_partial_k() {
    int gid = blockIdx.x * blockDim.x + threadIdx.x;
    int stride = gridDim.x * blockDim.x;
    for (int i = gid; i < NN; i += stride) {
        int od = g_odeg[i]; if (od < 1) od = 1;
        int id = g_ideg[i]; if (id < 1) id = 1;
        g_nout[i] = rsqrtf((float)od);
        g_nin[i]  = rsqrtf((float)id);
    }
    if (gid < SCAN_T) {
        int begin = gid * CHUNK;
        int endi  = begin + CHUNK; if (endi > NN) endi = NN;
        int sum = 0;
        if (begin < NN) {
            const int4* p = reinterpret_cast<const int4*>(g_ideg);
            #pragma unroll 13
            for (int i = begin / 4; i < endi / 4; i++) {
                int4 v = p[i];
                sum += v.x + v.y + v.z + v.w;
            }
        }
        g_part[gid] = sum;
    }
}

// Fused: shfl-based scan of g_part (1024) + per-chunk offset replay.
__global__ void __launch_bounds__(SCAN_T, 1) scan_offsets_k() {
    __shared__ int wsum[32];
    int t    = threadIdx.x;
    int lane = t & 31;
    int wid  = t >> 5;

    int own = g_part[t];
    int v = own;
    #pragma unroll
    for (int d = 1; d < 32; d <<= 1) {
        int n = __shfl_up_sync(0xffffffffu, v, d);
        if (lane >= d) v += n;
    }
    if (lane == 31) wsum[wid] = v;
    __syncthreads();
    if (wid == 0) {
        int w = wsum[lane];
        #pragma unroll
        for (int d = 1; d < 32; d <<= 1) {
            int n = __shfl_up_sync(0xffffffffu, w, d);
            if (lane >= d) w += n;
        }
        wsum[lane] = w;
    }
    __syncthreads();

    int excl = v - own + (wid > 0 ? wsum[wid - 1] : 0);

    int begin = t * CHUNK;
    int endi  = begin + CHUNK; if (endi > NN) endi = NN;
    int running = excl;
    for (int i = begin; i < endi; i++) {
        g_off[i] = running;
        g_cur[i] = running;
        running += g_ideg[i];
    }
    if (t == SCAN_T - 1) g_off[NN] = NE;
}

__global__ void scatter_k(const int* __restrict__ src, const int* __restrict__ dst) {
    int i0 = blockIdx.x * blockDim.x + threadIdx.x;
    int stride = gridDim.x * blockDim.x;
    for (int i = i0; i < NE; i += stride) {
        int d = dst[i];
        int pos = atomicAdd(&g_cur[d], 1);
        g_bucket[pos] = src[i];
    }
}

// ---------------- fp16 pre-scaled features ------------------------------------
// g_hx[n][f] = half(h[n][f] * nout[n]); folds the per-edge src scaling in.
__global__ void h2half_k(const float* __restrict__ h) {
    int i0 = blockIdx.x * blockDim.x + threadIdx.x;
    int stride = gridDim.x * blockDim.x;
    const float4* h4 = reinterpret_cast<const float4*>(h);
    uint2* o = reinterpret_cast<uint2*>(g_hx);
    for (int i = i0; i < NN * 32; i += stride) {   // 32 float4 per row
        int row = i >> 5;
        float s = g_nout[row];
        float4 v = h4[i];
        __half2 a = __floats2half2_rn(v.x * s, v.y * s);
        __half2 b = __floats2half2_rn(v.z * s, v.w * s);
        uint2 pkd;
        pkd.x = *reinterpret_cast<unsigned*>(&a);
        pkd.y = *reinterpret_cast<unsigned*>(&b);
        o[i] = pkd;
    }
}

// ---------------- layer-1 SpMM as fp16 gather ----------------------------------
__global__ void spmm1g_k() {
    unsigned w = (blockIdx.x * blockDim.x + threadIdx.x) >> 5;
    if (w >= NN) return;
    int lane = threadIdx.x & 31;
    int beg = g_off[w];
    int end = g_off[w + 1];
    const uint2* hx = reinterpret_cast<const uint2*>(g_hx);

    float4 acc = make_float4(0.f, 0.f, 0.f, 0.f);
    int e = beg;
    for (; e + 1 < end; e += 2) {
        int s0 = __ldg(&g_bucket[e]);
        int s1 = __ldg(&g_bucket[e + 1]);
        uint2 p0 = hx[(size_t)s0 * 32 + lane];
        uint2 p1 = hx[(size_t)s1 * 32 + lane];
        float2 a0 = __half22float2(*reinterpret_cast<__half2*>(&p0.x));
        float2 b0 = __half22float2(*reinterpret_cast<__half2*>(&p0.y));
        float2 a1 = __half22float2(*reinterpret_cast<__half2*>(&p1.x));
        float2 b1 = __half22float2(*reinterpret_cast<__half2*>(&p1.y));
        acc.x += a0.x + a1.x;  acc.y += a0.y + a1.y;
        acc.z += b0.x + b1.x;  acc.w += b0.y + b1.y;
    }
    if (e < end) {
        int s0 = __ldg(&g_bucket[e]);
        uint2 p0 = hx[(size_t)s0 * 32 + lane];
        float2 a0 = __half22float2(*reinterpret_cast<__half2*>(&p0.x));
        float2 b0 = __half22float2(*reinterpret_cast<__half2*>(&p0.y));
        acc.x += a0.x;  acc.y += a0.y;
        acc.z += b0.x;  acc.w += b0.y;
    }
    float ni = g_nin[w];
    acc.x *= ni; acc.y *= ni; acc.z *= ni; acc.w *= ni;
    reinterpret_cast<float4*>(g_ax)[(size_t)w * 32 + lane] = acc;
}

// ---------------- layer-2 SpMM as fp16 gather + fused epilogue -----------------
// One warp per dst node; lane holds 2 feats (one uint = half2).
__global__ void spmm2g_k(const float* __restrict__ b2, float* __restrict__ out) {
    unsigned w = (blockIdx.x * blockDim.x + threadIdx.x) >> 5;
    if (w >= NN) return;
    int lane = threadIdx.x & 31;
    int beg = g_off[w];
    int end = g_off[w + 1];
    const unsigned* y2 = reinterpret_cast<const unsigned*>(g_y2h);

    float2 acc = make_float2(0.f, 0.f);
    int e = beg;
    for (; e + 1 < end; e += 2) {
        int s0 = __ldg(&g_bucket[e]);
        int s1 = __ldg(&g_bucket[e + 1]);
        unsigned p0 = y2[(size_t)s0 * 32 + lane];
        unsigned p1 = y2[(size_t)s1 * 32 + lane];
        float2 v0 = __half22float2(*reinterpret_cast<__half2*>(&p0));
        float2 v1 = __half22float2(*reinterpret_cast<__half2*>(&p1));
        acc.x += v0.x + v1.x;
        acc.y += v0.y + v1.y;
    }
    if (e < end) {
        int s0 = __ldg(&g_bucket[e]);
        unsigned p0 = y2[(size_t)s0 * 32 + lane];
        float2 v0 = __half22float2(*reinterpret_cast<__half2*>(&p0));
        acc.x += v0.x;
        acc.y += v0.y;
    }
    float ni = g_nin[w];
    float2 bb = reinterpret_cast<const float2*>(b2)[lane];
    float2 o;
    o.x = fmaxf(fmaf(acc.x, ni, bb.x), 0.f);
    o.y = fmaxf(fmaf(acc.y, ni, bb.y), 0.f);
    reinterpret_cast<float2*>(out)[(size_t)w * 32 + lane] = o;
}

// ---------------- fused double-GEMM (f32x2, 128-row tiles) --------------------
static constexpr int FUSED_SMEM =
    (128 * 128 + 128 * 64 + 128 * 128 + 128) * (int)sizeof(float);

__global__ void __launch_bounds__(256, 1)
fused_mlp_k(const float* __restrict__ W1, const float* __restrict__ b1,
            const float* __restrict__ W2) {
    extern __shared__ float sm[];
    float* sW1 = sm;                        // [128][128] k-major
    float* sW2 = sm + 16384;                // [128][64]
    float* sA  = sm + 16384 + 8192;         // [128][128]  A^T: sA[k][m]; later H^T[c][m]
    float* sb  = sm + 16384 + 8192 + 16384; // [128]
    const int tid = threadIdx.x;

    {
        const float4* w1 = reinterpret_cast<const float4*>(W1);
        float4* d1 = reinterpret_cast<float4*>(sW1);
        #pragma unroll 4
        for (int i = tid; i < 4096; i += 256) d1[i] = w1[i];
        const float4* w2 = reinterpret_cast<const float4*>(W2);
        float4* d2 = reinterpret_cast<float4*>(sW2);
        #pragma unroll 2
        for (int i = tid; i < 2048; i += 256) d2[i] = w2[i];
        if (tid < 128) sb[tid] = b1[tid];
    }

    const int row0 = blockIdx.x * 128;

    {
        int m = tid >> 1;
        int q = tid & 1;
        int r = row0 + m;
        bool ok = (r < NN);
        const float4* ar =
            reinterpret_cast<const float4*>(g_ax + (size_t)(ok ? r : 0) * 128);
        #pragma unroll
        for (int kk = 0; kk < 16; kk++) {
            int k4 = q * 16 + kk;
            float4 v = ok ? ar[k4] : make_float4(0.f, 0.f, 0.f, 0.f);
            sA[(k4 * 4 + 0) * 128 + m] = v.x;
            sA[(k4 * 4 + 1) * 128 + m] = v.y;
            sA[(k4 * 4 + 2) * 128 + m] = v.z;
            sA[(k4 * 4 + 3) * 128 + m] = v.w;
        }
    }
    __syncthreads();

    const int tm = tid & 15;
    const int tn = tid >> 4;

    float hv[8][8];
    {
        unsigned long long acc[4][8];
        #pragma unroll
        for (int p = 0; p < 4; p++)
            #pragma unroll
            for (int i = 0; i < 8; i++) acc[p][i] = 0ull;

        #pragma unroll 4
        for (int k = 0; k < 128; k++) {
            ulonglong2 aA = *reinterpret_cast<const ulonglong2*>(sA + k * 128 + tm * 8);
            ulonglong2 aB = *reinterpret_cast<const ulonglong2*>(sA + k * 128 + tm * 8 + 4);
            float4 b0 = *reinterpret_cast<const float4*>(sW1 + k * 128 + tn * 8);
            float4 b1v = *reinterpret_cast<const float4*>(sW1 + k * 128 + tn * 8 + 4);
            unsigned long long ap[4] = {aA.x, aA.y, aB.x, aB.y};
            unsigned long long bd[8] = {pack2(b0.x),  pack2(b0.y),  pack2(b0.z),  pack2(b0.w),
                                        pack2(b1v.x), pack2(b1v.y), pack2(b1v.z), pack2(b1v.w)};
            #pragma unroll
            for (int p = 0; p < 4; p++)
                #pragma unroll
                for (int i = 0; i < 8; i++)
                    fma2(acc[p][i], ap[p], bd[i]);
        }

        float no[8];
        #pragma unroll
        for (int j = 0; j < 8; j++) {
            int r = row0 + tm * 8 + j;
            no[j] = (r < NN) ? g_nout[r] : 0.f;
        }
        #pragma unroll
        for (int i = 0; i < 8; i++) {
            float bb = sb[tn * 8 + i];
            #pragma unroll
            for (int p = 0; p < 4; p++) {
                float2 v = unpk(acc[p][i]);
                hv[2 * p + 0][i] = fmaxf(v.x + bb, 0.f) * no[2 * p + 0];
                hv[2 * p + 1][i] = fmaxf(v.y + bb, 0.f) * no[2 * p + 1];
            }
        }
    }

    __syncthreads();

    #pragma unroll
    for (int i = 0; i < 8; i++) {
        int c = tn * 8 + i;
        float4 v0 = make_float4(hv[0][i], hv[1][i], hv[2][i], hv[3][i]);
        float4 v1 = make_float4(hv[4][i], hv[5][i], hv[6][i], hv[7][i]);
        *reinterpret_cast<float4*>(sA + c * 128 + tm * 8)     = v0;
        *reinterpret_cast<float4*>(sA + c * 128 + tm * 8 + 4) = v1;
    }
    __syncthreads();

    {
        unsigned long long acc[4][4];
        #pragma unroll
        for (int p = 0; p < 4; p++)
            #pragma unroll
            for (int i = 0; i < 4; i++) acc[p][i] = 0ull;

        #pragma unroll 4
        for (int k = 0; k < 128; k++) {
            ulonglong2 aA = *reinterpret_cast<const ulonglong2*>(sA + k * 128 + tm * 8);
            ulonglong2 aB = *reinterpret_cast<const ulonglong2*>(sA + k * 128 + tm * 8 + 4);
            float4 b = *reinterpret_cast<const float4*>(sW2 + k * 64 + tn * 4);
            unsigned long long ap[4] = {aA.x, aA.y, aB.x, aB.y};
            unsigned long long bd[4] = {pack2(b.x), pack2(b.y), pack2(b.z), pack2(b.w)};
            #pragma unroll
            for (int p = 0; p < 4; p++)
                #pragma unroll
                for (int i = 0; i < 4; i++)
                    fma2(acc[p][i], ap[p], bd[i]);
        }

        // epilogue: write y2 rows as fp16 (two half2 = 8B per row-segment)
        #pragma unroll
        for (int p = 0; p < 4; p++) {
            float2 c0 = unpk(acc[p][0]);
            float2 c1 = unpk(acc[p][1]);
            float2 c2 = unpk(acc[p][2]);
            float2 c3 = unpk(acc[p][3]);
            int r0r = row0 + tm * 8 + 2 * p;
            if (r0r < NN) {
                __half2 a = __floats2half2_rn(c0.x, c1.x);
                __half2 b = __floats2half2_rn(c2.x, c3.x);
                uint2 pkd;
                pkd.x = *reinterpret_cast<unsigned*>(&a);
                pkd.y = *reinterpret_cast<unsigned*>(&b);
                *reinterpret_cast<uint2*>(g_y2h + (size_t)r0r * 64 + tn * 4) = pkd;
            }
            if (r0r + 1 < NN) {
                __half2 a = __floats2half2_rn(c0.y, c1.y);
                __half2 b = __floats2half2_rn(c2.y, c3.y);
                uint2 pkd;
                pkd.x = *reinterpret_cast<unsigned*>(&a);
                pkd.y = *reinterpret_cast<unsigned*>(&b);
                *reinterpret_cast<uint2*>(g_y2h + (size_t)(r0r + 1) * 64 + tn * 4) = pkd;
            }
        }
    }
}

// ---------------- launch ------------------------------------------------------

extern "C" void kernel_launch(void* const* d_in, const int* in_sizes, int n_in,
                              void* d_out, int out_size) {
    const float* h  = (const float*)d_in[0];
    const float* W1 = (const float*)d_in[1];
    const float* b1 = (const float*)d_in[2];
    const float* W2 = (const float*)d_in[3];
    const float* b2 = (const float*)d_in[4];
    const int*   src = (const int*)d_in[5];
    const int*   dst = (const int*)d_in[6];
    float* out = (float*)d_out;
    (void)in_sizes; (void)n_in; (void)out_size;

    cudaFuncSetAttribute(fused_mlp_k,
                         cudaFuncAttributeMaxDynamicSharedMemorySize, FUSED_SMEM);

    void* odeg_p = nullptr; void* ideg_p = nullptr;
    cudaGetSymbolAddress(&odeg_p, g_odeg);
    cudaGetSymbolAddress(&ideg_p, g_ideg);
    cudaMemsetAsync(odeg_p, 0, NN * sizeof(int));
    cudaMemsetAsync(ideg_p, 0, NN * sizeof(int));

    degree_k<<<1024, 256>>>(src, dst);
    norm_partial_k<<<98, 512>>>();     // norms + scan phase A fused
    scan_offsets_k<<<1, SCAN_T>>>();   // shfl scan + offsets fused
    h2half_k<<<1024, 256>>>(h);        // fp16 pre-scaled features
    scatter_k<<<1024, 256>>>(src, dst);
    spmm1g_k<<<(NN * 32 + 255) / 256, 256>>>();             // 1 warp/node, fp16 gather
    fused_mlp_k<<<(NN + 127) / 128, 256, FUSED_SMEM>>>(W1, b1, W2);
    spmm2g_k<<<(NN * 32 + 255) / 256, 256>>>(b2, out);      // 1 warp/node, fp16 gather
}

// round 11
// speedup vs baseline: 1.3539x; 1.3539x over previous
#include <cuda_runtime.h>
#include <cuda_fp16.h>

// Problem constants (fixed by the dataset)
static constexpr int NN = 50000;   // nodes
static constexpr int NE = 800000;  // edges
// features: 128 -> 128 (hidden) -> 64 (out)

// scan decomposition (CHUNK divisible by 4 for int4 loads)
static constexpr int SCAN_T = 1024;
static constexpr int CHUNK  = 52;          // 1024*52 = 53248 >= NN

// ---------------- scratch (__device__ globals; no allocs allowed) ------------
__device__ float  g_ax [(size_t)NN * 128]; // nin-scaled layer1 aggregate (GEMM input A)
__device__ __half g_y2h[(size_t)NN * 64];  // (relu(h1)*nout) @ W2, fp16
__device__ __half g_hx [(size_t)NN * 128]; // h * nout, fp16 (layer1 gather source)
__device__ int    g_odeg[NN];
__device__ int    g_ideg[NN];
__device__ float  g_nout[NN];
__device__ float  g_nin [NN];
__device__ int    g_off [NN + 1];          // CSR offsets (by dst)
__device__ int    g_cur [NN];              // scatter cursors
__device__ int    g_bucket[NE];            // src ids grouped by dst
__device__ int    g_part[SCAN_T];          // per-chunk partial sums
__device__ int    g_pref[SCAN_T];          // exclusive prefix of partials

// ---------------- packed f32x2 helpers (PTX-only) -----------------------------
__device__ __forceinline__ void fma2(unsigned long long& d,
                                     unsigned long long a,
                                     unsigned long long b) {
    asm("fma.rn.f32x2 %0, %1, %2, %0;" : "+l"(d) : "l"(a), "l"(b));
}
__device__ __forceinline__ unsigned long long pack2(float x) {
    unsigned long long r;
    asm("mov.b64 %0, {%1, %1};" : "=l"(r) : "f"(x));
    return r;
}
__device__ __forceinline__ float2 unpk(unsigned long long v) {
    float lo, hi;
    asm("mov.b64 {%0, %1}, %2;" : "=f"(lo), "=f"(hi) : "l"(v));
    return make_float2(lo, hi);
}

// ---------------- graph preprocessing ----------------------------------------

__global__ void degree_k(const int* __restrict__ src, const int* __restrict__ dst) {
    int i0 = blockIdx.x * blockDim.x + threadIdx.x;
    int stride = gridDim.x * blockDim.x;
    for (int i = i0; i < NE; i += stride) {
        atomicAdd(&g_odeg[src[i]], 1);
        atomicAdd(&g_ideg[dst[i]], 1);
    }
}

// norms (grid-stride) + per-chunk partial degree sums (first SCAN_T threads)
__global__ void norm_partial_k() {
    int gid = blockIdx.x * blockDim.x + threadIdx.x;
    int stride = gridDim.x * blockDim.x;
    for (int i = gid; i < NN; i += stride) {
        int od = g_odeg[i]; if (od < 1) od = 1;
        int id = g_ideg[i]; if (id < 1) id = 1;
        g_nout[i] = rsqrtf((float)od);
        g_nin[i]  = rsqrtf((float)id);
    }
    if (gid < SCAN_T) {
        int begin = gid * CHUNK;
        int endi  = begin + CHUNK; if (endi > NN) endi = NN;
        int sum = 0;
        if (begin < NN) {
            const int4* p = reinterpret_cast<const int4*>(g_ideg);
            #pragma unroll 13
            for (int i = begin / 4; i < endi / 4; i++) {
                int4 v = p[i];
                sum += v.x + v.y + v.z + v.w;
            }
        }
        g_part[gid] = sum;
    }
}

// shfl-based exclusive scan of the 1024 partials (registers + 32-word SMEM only)
__global__ void __launch_bounds__(SCAN_T, 1) scanpart_k() {
    __shared__ int wsum[32];
    int t    = threadIdx.x;
    int lane = t & 31;
    int wid  = t >> 5;

    int own = g_part[t];
    int v = own;
    #pragma unroll
    for (int d = 1; d < 32; d <<= 1) {
        int n = __shfl_up_sync(0xffffffffu, v, d);
        if (lane >= d) v += n;
    }
    if (lane == 31) wsum[wid] = v;
    __syncthreads();
    if (wid == 0) {
        int w = wsum[lane];
        #pragma unroll
        for (int d = 1; d < 32; d <<= 1) {
            int n = __shfl_up_sync(0xffffffffu, w, d);
            if (lane >= d) w += n;
        }
        wsum[lane] = w;
    }
    __syncthreads();

    g_pref[t] = v - own + (wid > 0 ? wsum[wid - 1] : 0);
}

// parallel offsets replay across 8 CTAs (do NOT fuse into one CTA)
__global__ void offsets_k() {
    int t = blockIdx.x * blockDim.x + threadIdx.x;
    if (t >= SCAN_T) return;
    int begin = t * CHUNK;
    int endi  = begin + CHUNK; if (endi > NN) endi = NN;
    int running = g_pref[t];
    for (int i = begin; i < endi; i++) {
        g_off[i] = running;
        g_cur[i] = running;
        running += g_ideg[i];
    }
    if (t == SCAN_T - 1) g_off[NN] = NE;
}

__global__ void scatter_k(const int* __restrict__ src, const int* __restrict__ dst) {
    int i0 = blockIdx.x * blockDim.x + threadIdx.x;
    int stride = gridDim.x * blockDim.x;
    for (int i = i0; i < NE; i += stride) {
        int d = dst[i];
        int pos = atomicAdd(&g_cur[d], 1);
        g_bucket[pos] = src[i];
    }
}

// ---------------- fp16 pre-scaled features ------------------------------------
// g_hx[n][f] = half(h[n][f] * nout[n]); folds the per-edge src scaling in.
__global__ void h2half_k(const float* __restrict__ h) {
    int i0 = blockIdx.x * blockDim.x + threadIdx.x;
    int stride = gridDim.x * blockDim.x;
    const float4* h4 = reinterpret_cast<const float4*>(h);
    uint2* o = reinterpret_cast<uint2*>(g_hx);
    for (int i = i0; i < NN * 32; i += stride) {   // 32 float4 per row
        int row = i >> 5;
        float s = g_nout[row];
        float4 v = h4[i];
        __half2 a = __floats2half2_rn(v.x * s, v.y * s);
        __half2 b = __floats2half2_rn(v.z * s, v.w * s);
        uint2 pkd;
        pkd.x = *reinterpret_cast<unsigned*>(&a);
        pkd.y = *reinterpret_cast<unsigned*>(&b);
        o[i] = pkd;
    }
}

// ---------------- layer-1 SpMM as fp16 gather ----------------------------------
__global__ void spmm1g_k() {
    unsigned w = (blockIdx.x * blockDim.x + threadIdx.x) >> 5;
    if (w >= NN) return;
    int lane = threadIdx.x & 31;
    int beg = g_off[w];
    int end = g_off[w + 1];
    const uint2* hx = reinterpret_cast<const uint2*>(g_hx);

    float4 acc = make_float4(0.f, 0.f, 0.f, 0.f);
    int e = beg;
    for (; e + 1 < end; e += 2) {
        int s0 = __ldg(&g_bucket[e]);
        int s1 = __ldg(&g_bucket[e + 1]);
        uint2 p0 = hx[(size_t)s0 * 32 + lane];
        uint2 p1 = hx[(size_t)s1 * 32 + lane];
        float2 a0 = __half22float2(*reinterpret_cast<__half2*>(&p0.x));
        float2 b0 = __half22float2(*reinterpret_cast<__half2*>(&p0.y));
        float2 a1 = __half22float2(*reinterpret_cast<__half2*>(&p1.x));
        float2 b1 = __half22float2(*reinterpret_cast<__half2*>(&p1.y));
        acc.x += a0.x + a1.x;  acc.y += a0.y + a1.y;
        acc.z += b0.x + b1.x;  acc.w += b0.y + b1.y;
    }
    if (e < end) {
        int s0 = __ldg(&g_bucket[e]);
        uint2 p0 = hx[(size_t)s0 * 32 + lane];
        float2 a0 = __half22float2(*reinterpret_cast<__half2*>(&p0.x));
        float2 b0 = __half22float2(*reinterpret_cast<__half2*>(&p0.y));
        acc.x += a0.x;  acc.y += a0.y;
        acc.z += b0.x;  acc.w += b0.y;
    }
    float ni = g_nin[w];
    acc.x *= ni; acc.y *= ni; acc.z *= ni; acc.w *= ni;
    reinterpret_cast<float4*>(g_ax)[(size_t)w * 32 + lane] = acc;
}

// ---------------- layer-2 SpMM as fp16 gather + fused epilogue -----------------
// One warp per dst node; lane holds 2 feats (one uint = half2).
__global__ void spmm2g_k(const float* __restrict__ b2, float* __restrict__ out) {
    unsigned w = (blockIdx.x * blockDim.x + threadIdx.x) >> 5;
    if (w >= NN) return;
    int lane = threadIdx.x & 31;
    int beg = g_off[w];
    int end = g_off[w + 1];
    const unsigned* y2 = reinterpret_cast<const unsigned*>(g_y2h);

    float2 acc = make_float2(0.f, 0.f);
    int e = beg;
    for (; e + 1 < end; e += 2) {
        int s0 = __ldg(&g_bucket[e]);
        int s1 = __ldg(&g_bucket[e + 1]);
        unsigned p0 = y2[(size_t)s0 * 32 + lane];
        unsigned p1 = y2[(size_t)s1 * 32 + lane];
        float2 v0 = __half22float2(*reinterpret_cast<__half2*>(&p0));
        float2 v1 = __half22float2(*reinterpret_cast<__half2*>(&p1));
        acc.x += v0.x + v1.x;
        acc.y += v0.y + v1.y;
    }
    if (e < end) {
        int s0 = __ldg(&g_bucket[e]);
        unsigned p0 = y2[(size_t)s0 * 32 + lane];
        float2 v0 = __half22float2(*reinterpret_cast<__half2*>(&p0));
        acc.x += v0.x;
        acc.y += v0.y;
    }
    float ni = g_nin[w];
    float2 bb = reinterpret_cast<const float2*>(b2)[lane];
    float2 o;
    o.x = fmaxf(fmaf(acc.x, ni, bb.x), 0.f);
    o.y = fmaxf(fmaf(acc.y, ni, bb.y), 0.f);
    reinterpret_cast<float2*>(out)[(size_t)w * 32 + lane] = o;
}

// ---------------- fused double-GEMM (f32x2, 128-row tiles) --------------------
static constexpr int FUSED_SMEM =
    (128 * 128 + 128 * 64 + 128 * 128 + 128) * (int)sizeof(float);

__global__ void __launch_bounds__(256, 1)
fused_mlp_k(const float* __restrict__ W1, const float* __restrict__ b1,
            const float* __restrict__ W2) {
    extern __shared__ float sm[];
    float* sW1 = sm;                        // [128][128] k-major
    float* sW2 = sm + 16384;                // [128][64]
    float* sA  = sm + 16384 + 8192;         // [128][128]  A^T: sA[k][m]; later H^T[c][m]
    float* sb  = sm + 16384 + 8192 + 16384; // [128]
    const int tid = threadIdx.x;

    {
        const float4* w1 = reinterpret_cast<const float4*>(W1);
        float4* d1 = reinterpret_cast<float4*>(sW1);
        #pragma unroll 4
        for (int i = tid; i < 4096; i += 256) d1[i] = w1[i];
        const float4* w2 = reinterpret_cast<const float4*>(W2);
        float4* d2 = reinterpret_cast<float4*>(sW2);
        #pragma unroll 2
        for (int i = tid; i < 2048; i += 256) d2[i] = w2[i];
        if (tid < 128) sb[tid] = b1[tid];
    }

    const int row0 = blockIdx.x * 128;

    {
        int m = tid >> 1;
        int q = tid & 1;
        int r = row0 + m;
        bool ok = (r < NN);
        const float4* ar =
            reinterpret_cast<const float4*>(g_ax + (size_t)(ok ? r : 0) * 128);
        #pragma unroll
        for (int kk = 0; kk < 16; kk++) {
            int k4 = q * 16 + kk;
            float4 v = ok ? ar[k4] : make_float4(0.f, 0.f, 0.f, 0.f);
            sA[(k4 * 4 + 0) * 128 + m] = v.x;
            sA[(k4 * 4 + 1) * 128 + m] = v.y;
            sA[(k4 * 4 + 2) * 128 + m] = v.z;
            sA[(k4 * 4 + 3) * 128 + m] = v.w;
        }
    }
    __syncthreads();

    const int tm = tid & 15;
    const int tn = tid >> 4;

    float hv[8][8];
    {
        unsigned long long acc[4][8];
        #pragma unroll
        for (int p = 0; p < 4; p++)
            #pragma unroll
            for (int i = 0; i < 8; i++) acc[p][i] = 0ull;

        #pragma unroll 4
        for (int k = 0; k < 128; k++) {
            ulonglong2 aA = *reinterpret_cast<const ulonglong2*>(sA + k * 128 + tm * 8);
            ulonglong2 aB = *reinterpret_cast<const ulonglong2*>(sA + k * 128 + tm * 8 + 4);
            float4 b0 = *reinterpret_cast<const float4*>(sW1 + k * 128 + tn * 8);
            float4 b1v = *reinterpret_cast<const float4*>(sW1 + k * 128 + tn * 8 + 4);
            unsigned long long ap[4] = {aA.x, aA.y, aB.x, aB.y};
            unsigned long long bd[8] = {pack2(b0.x),  pack2(b0.y),  pack2(b0.z),  pack2(b0.w),
                                        pack2(b1v.x), pack2(b1v.y), pack2(b1v.z), pack2(b1v.w)};
            #pragma unroll
            for (int p = 0; p < 4; p++)
                #pragma unroll
                for (int i = 0; i < 8; i++)
                    fma2(acc[p][i], ap[p], bd[i]);
        }

        float no[8];
        #pragma unroll
        for (int j = 0; j < 8; j++) {
            int r = row0 + tm * 8 + j;
            no[j] = (r < NN) ? g_nout[r] : 0.f;
        }
        #pragma unroll
        for (int i = 0; i < 8; i++) {
            float bb = sb[tn * 8 + i];
            #pragma unroll
            for (int p = 0; p < 4; p++) {
                float2 v = unpk(acc[p][i]);
                hv[2 * p + 0][i] = fmaxf(v.x + bb, 0.f) * no[2 * p + 0];
                hv[2 * p + 1][i] = fmaxf(v.y + bb, 0.f) * no[2 * p + 1];
            }
        }
    }

    __syncthreads();

    #pragma unroll
    for (int i = 0; i < 8; i++) {
        int c = tn * 8 + i;
        float4 v0 = make_float4(hv[0][i], hv[1][i], hv[2][i], hv[3][i]);
        float4 v1 = make_float4(hv[4][i], hv[5][i], hv[6][i], hv[7][i]);
        *reinterpret_cast<float4*>(sA + c * 128 + tm * 8)     = v0;
        *reinterpret_cast<float4*>(sA + c * 128 + tm * 8 + 4) = v1;
    }
    __syncthreads();

    {
        unsigned long long acc[4][4];
        #pragma unroll
        for (int p = 0; p < 4; p++)
            #pragma unroll
            for (int i = 0; i < 4; i++) acc[p][i] = 0ull;

        #pragma unroll 4
        for (int k = 0; k < 128; k++) {
            ulonglong2 aA = *reinterpret_cast<const ulonglong2*>(sA + k * 128 + tm * 8);
            ulonglong2 aB = *reinterpret_cast<const ulonglong2*>(sA + k * 128 + tm * 8 + 4);
            float4 b = *reinterpret_cast<const float4*>(sW2 + k * 64 + tn * 4);
            unsigned long long ap[4] = {aA.x, aA.y, aB.x, aB.y};
            unsigned long long bd[4] = {pack2(b.x), pack2(b.y), pack2(b.z), pack2(b.w)};
            #pragma unroll
            for (int p = 0; p < 4; p++)
                #pragma unroll
                for (int i = 0; i < 4; i++)
                    fma2(acc[p][i], ap[p], bd[i]);
        }

        // epilogue: write y2 rows as fp16 (two half2 = 8B per row-segment)
        #pragma unroll
        for (int p = 0; p < 4; p++) {
            float2 c0 = unpk(acc[p][0]);
            float2 c1 = unpk(acc[p][1]);
            float2 c2 = unpk(acc[p][2]);
            float2 c3 = unpk(acc[p][3]);
            int r0r = row0 + tm * 8 + 2 * p;
            if (r0r < NN) {
                __half2 a = __floats2half2_rn(c0.x, c1.x);
                __half2 b = __floats2half2_rn(c2.x, c3.x);
                uint2 pkd;
                pkd.x = *reinterpret_cast<unsigned*>(&a);
                pkd.y = *reinterpret_cast<unsigned*>(&b);
                *reinterpret_cast<uint2*>(g_y2h + (size_t)r0r * 64 + tn * 4) = pkd;
            }
            if (r0r + 1 < NN) {
                __half2 a = __floats2half2_rn(c0.y, c1.y);
                __half2 b = __floats2half2_rn(c2.y, c3.y);
                uint2 pkd;
                pkd.x = *reinterpret_cast<unsigned*>(&a);
                pkd.y = *reinterpret_cast<unsigned*>(&b);
                *reinterpret_cast<uint2*>(g_y2h + (size_t)(r0r + 1) * 64 + tn * 4) = pkd;
            }
        }
    }
}

// ---------------- launch ------------------------------------------------------

extern "C" void kernel_launch(void* const* d_in, const int* in_sizes, int n_in,
                              void* d_out, int out_size) {
    const float* h  = (const float*)d_in[0];
    const float* W1 = (const float*)d_in[1];
    const float* b1 = (const float*)d_in[2];
    const float* W2 = (const float*)d_in[3];
    const float* b2 = (const float*)d_in[4];
    const int*   src = (const int*)d_in[5];
    const int*   dst = (const int*)d_in[6];
    float* out = (float*)d_out;
    (void)in_sizes; (void)n_in; (void)out_size;

    cudaFuncSetAttribute(fused_mlp_k,
                         cudaFuncAttributeMaxDynamicSharedMemorySize, FUSED_SMEM);

    void* odeg_p = nullptr; void* ideg_p = nullptr;
    cudaGetSymbolAddress(&odeg_p, g_odeg);
    cudaGetSymbolAddress(&ideg_p, g_ideg);
    cudaMemsetAsync(odeg_p, 0, NN * sizeof(int));
    cudaMemsetAsync(ideg_p, 0, NN * sizeof(int));

    degree_k<<<1024, 256>>>(src, dst);
    norm_partial_k<<<98, 512>>>();     // norms + scan phase A fused
    scanpart_k<<<1, SCAN_T>>>();       // shfl scan (registers/SMEM only)
    h2half_k<<<1024, 256>>>(h);        // fp16 pre-scaled features
    offsets_k<<<8, 128>>>();           // parallel replay across 8 SMs
    scatter_k<<<1024, 256>>>(src, dst);
    spmm1g_k<<<(NN * 32 + 255) / 256, 256>>>();             // 1 warp/node, fp16 gather
    fused_mlp_k<<<(NN + 127) / 128, 256, FUSED_SMEM>>>(W1, b1, W2);
    spmm2g_k<<<(NN * 32 + 255) / 256, 256>>>(b2, out);      // 1 warp/node, fp16 gather
}

// round 13
// speedup vs baseline: 1.7299x; 1.2777x over previous
#include <cuda_runtime.h>
#include <cuda_fp16.h>
#include <mma.h>
#include <cstdint>

using namespace nvcuda;

// Problem constants (fixed by the dataset)
static constexpr int NN = 50000;   // nodes
static constexpr int NE = 800000;  // edges
// features: 128 -> 128 (hidden) -> 64 (out)

// scan decomposition
static constexpr int SCAN_T = 1024;
static constexpr int CHUNK  = 52;          // 1024*52 = 53248 >= NN

// ---------------- scratch (__device__ globals; no allocs allowed) ------------
__device__ __half g_axh[(size_t)NN * 128]; // nin-scaled layer1 aggregate, fp16 (GEMM A)
__device__ __half g_y2h[(size_t)NN * 64];  // (relu(h1)*nout) @ W2, fp16
__device__ __half g_hx [(size_t)NN * 128]; // h * nout, fp16 (layer1 gather source)
__device__ int    g_odeg[NN];
__device__ int    g_ideg[NN];
__device__ float  g_nout[NN];
__device__ float  g_nin [NN];
__device__ int    g_off [NN + 1];
__device__ int    g_cur [NN];
__device__ int    g_bucket[NE];
__device__ int    g_part[SCAN_T];
__device__ int    g_pref[SCAN_T];

// ---------------- graph preprocessing ----------------------------------------

__global__ void degree_k(const int* __restrict__ src, const int* __restrict__ dst) {
    int i0 = blockIdx.x * blockDim.x + threadIdx.x;
    int stride = gridDim.x * blockDim.x;
    for (int i = i0; i < NE; i += stride) {
        atomicAdd(&g_odeg[src[i]], 1);
        atomicAdd(&g_ideg[dst[i]], 1);
    }
}

__global__ void norm_partial_k() {
    int gid = blockIdx.x * blockDim.x + threadIdx.x;
    int stride = gridDim.x * blockDim.x;
    for (int i = gid; i < NN; i += stride) {
        int od = g_odeg[i]; if (od < 1) od = 1;
        int id = g_ideg[i]; if (id < 1) id = 1;
        g_nout[i] = rsqrtf((float)od);
        g_nin[i]  = rsqrtf((float)id);
    }
    if (gid < SCAN_T) {
        int begin = gid * CHUNK;
        int endi  = begin + CHUNK; if (endi > NN) endi = NN;
        int sum = 0;
        if (begin < NN) {
            const int4* p = reinterpret_cast<const int4*>(g_ideg);
            #pragma unroll 13
            for (int i = begin / 4; i < endi / 4; i++) {
                int4 v = p[i];
                sum += v.x + v.y + v.z + v.w;
            }
        }
        g_part[gid] = sum;
    }
}

__global__ void __launch_bounds__(SCAN_T, 1) scanpart_k() {
    __shared__ int wsum[32];
    int t    = threadIdx.x;
    int lane = t & 31;
    int wid  = t >> 5;

    int own = g_part[t];
    int v = own;
    #pragma unroll
    for (int d = 1; d < 32; d <<= 1) {
        int n = __shfl_up_sync(0xffffffffu, v, d);
        if (lane >= d) v += n;
    }
    if (lane == 31) wsum[wid] = v;
    __syncthreads();
    if (wid == 0) {
        int w = wsum[lane];
        #pragma unroll
        for (int d = 1; d < 32; d <<= 1) {
            int n = __shfl_up_sync(0xffffffffu, w, d);
            if (lane >= d) w += n;
        }
        wsum[lane] = w;
    }
    __syncthreads();

    g_pref[t] = v - own + (wid > 0 ? wsum[wid - 1] : 0);
}

__global__ void offsets_k() {
    int t = blockIdx.x * blockDim.x + threadIdx.x;
    if (t >= SCAN_T) return;
    int begin = t * CHUNK;
    int endi  = begin + CHUNK; if (endi > NN) endi = NN;
    int running = g_pref[t];
    for (int i = begin; i < endi; i++) {
        g_off[i] = running;
        g_cur[i] = running;
        running += g_ideg[i];
    }
    if (t == SCAN_T - 1) g_off[NN] = NE;
}

__global__ void scatter_k(const int* __restrict__ src, const int* __restrict__ dst) {
    int i0 = blockIdx.x * blockDim.x + threadIdx.x;
    int stride = gridDim.x * blockDim.x;
    for (int i = i0; i < NE; i += stride) {
        int d = dst[i];
        int pos = atomicAdd(&g_cur[d], 1);
        g_bucket[pos] = src[i];
    }
}

// ---------------- fp16 pre-scaled features ------------------------------------
__global__ void h2half_k(const float* __restrict__ h) {
    int i0 = blockIdx.x * blockDim.x + threadIdx.x;
    int stride = gridDim.x * blockDim.x;
    const float4* h4 = reinterpret_cast<const float4*>(h);
    uint2* o = reinterpret_cast<uint2*>(g_hx);
    for (int i = i0; i < NN * 32; i += stride) {
        int row = i >> 5;
        float s = g_nout[row];
        float4 v = h4[i];
        __half2 a = __floats2half2_rn(v.x * s, v.y * s);
        __half2 b = __floats2half2_rn(v.z * s, v.w * s);
        uint2 pkd;
        pkd.x = *reinterpret_cast<unsigned*>(&a);
        pkd.y = *reinterpret_cast<unsigned*>(&b);
        o[i] = pkd;
    }
}

// ---------------- layer-1 SpMM as fp16 gather -> fp16 A ------------------------
__global__ void spmm1g_k() {
    unsigned w = (blockIdx.x * blockDim.x + threadIdx.x) >> 5;
    if (w >= NN) return;
    int lane = threadIdx.x & 31;
    int beg = g_off[w];
    int end = g_off[w + 1];
    const uint2* hx = reinterpret_cast<const uint2*>(g_hx);

    float4 acc = make_float4(0.f, 0.f, 0.f, 0.f);
    int e = beg;
    for (; e + 1 < end; e += 2) {
        int s0 = __ldg(&g_bucket[e]);
        int s1 = __ldg(&g_bucket[e + 1]);
        uint2 p0 = hx[(size_t)s0 * 32 + lane];
        uint2 p1 = hx[(size_t)s1 * 32 + lane];
        float2 a0 = __half22float2(*reinterpret_cast<__half2*>(&p0.x));
        float2 b0 = __half22float2(*reinterpret_cast<__half2*>(&p0.y));
        float2 a1 = __half22float2(*reinterpret_cast<__half2*>(&p1.x));
        float2 b1 = __half22float2(*reinterpret_cast<__half2*>(&p1.y));
        acc.x += a0.x + a1.x;  acc.y += a0.y + a1.y;
        acc.z += b0.x + b1.x;  acc.w += b0.y + b1.y;
    }
    if (e < end) {
        int s0 = __ldg(&g_bucket[e]);
        uint2 p0 = hx[(size_t)s0 * 32 + lane];
        float2 a0 = __half22float2(*reinterpret_cast<__half2*>(&p0.x));
        float2 b0 = __half22float2(*reinterpret_cast<__half2*>(&p0.y));
        acc.x += a0.x;  acc.y += a0.y;
        acc.z += b0.x;  acc.w += b0.y;
    }
    float ni = g_nin[w];
    __half2 h0 = __floats2half2_rn(acc.x * ni, acc.y * ni);
    __half2 h1 = __floats2half2_rn(acc.z * ni, acc.w * ni);
    uint2 pkd;
    pkd.x = *reinterpret_cast<unsigned*>(&h0);
    pkd.y = *reinterpret_cast<unsigned*>(&h1);
    reinterpret_cast<uint2*>(g_axh)[(size_t)w * 32 + lane] = pkd;
}

// ---------------- layer-2 SpMM as fp16 gather + fused epilogue -----------------
__global__ void spmm2g_k(const float* __restrict__ b2, float* __restrict__ out) {
    unsigned w = (blockIdx.x * blockDim.x + threadIdx.x) >> 5;
    if (w >= NN) return;
    int lane = threadIdx.x & 31;
    int beg = g_off[w];
    int end = g_off[w + 1];
    const unsigned* y2 = reinterpret_cast<const unsigned*>(g_y2h);

    float2 acc = make_float2(0.f, 0.f);
    int e = beg;
    for (; e + 1 < end; e += 2) {
        int s0 = __ldg(&g_bucket[e]);
        int s1 = __ldg(&g_bucket[e + 1]);
        unsigned p0 = y2[(size_t)s0 * 32 + lane];
        unsigned p1 = y2[(size_t)s1 * 32 + lane];
        float2 v0 = __half22float2(*reinterpret_cast<__half2*>(&p0));
        float2 v1 = __half22float2(*reinterpret_cast<__half2*>(&p1));
        acc.x += v0.x + v1.x;
        acc.y += v0.y + v1.y;
    }
    if (e < end) {
        int s0 = __ldg(&g_bucket[e]);
        unsigned p0 = y2[(size_t)s0 * 32 + lane];
        float2 v0 = __half22float2(*reinterpret_cast<__half2*>(&p0));
        acc.x += v0.x;
        acc.y += v0.y;
    }
    float ni = g_nin[w];
    float2 bb = reinterpret_cast<const float2*>(b2)[lane];
    float2 o;
    o.x = fmaxf(fmaf(acc.x, ni, bb.x), 0.f);
    o.y = fmaxf(fmaf(acc.y, ni, bb.y), 0.f);
    reinterpret_cast<float2*>(out)[(size_t)w * 32 + lane] = o;
}

// ================= wmma (HMMA) fused double-GEMM ==============================
// Per 128-node tile: H = relu(A@W1 + b1)*nout ; y2 = H@W2  (fp16 in, fp32 acc)

static constexpr int LDA  = 136;   // halves, padded (272B rows; 16B multiple)
static constexpr int LDW2 = 72;    // halves (144B)
static constexpr int LDC  = 132;   // floats (528B)

static constexpr int OFF_A  = 0;                         // [128][LDA] half  (A, then H)
static constexpr int OFF_W1 = OFF_A  + 128 * LDA * 2;    // [128][LDA] half  ([k][n])
static constexpr int OFF_W2 = OFF_W1 + 128 * LDA * 2;    // [128][LDW2] half ([k][n])
static constexpr int OFF_C  = OFF_W2 + 128 * LDW2 * 2;   // [128][LDC] float (staging)
static constexpr int OFF_B1 = OFF_C  + 128 * LDC * 4;    // [128] float
static constexpr int WMMA_SMEM = OFF_B1 + 512;

__global__ void __launch_bounds__(256, 1)
fused_mlp_wmma(const float* __restrict__ W1, const float* __restrict__ b1,
               const float* __restrict__ W2) {
    extern __shared__ char smem[];
    __half* sA  = reinterpret_cast<__half*>(smem + OFF_A);
    __half* sW1 = reinterpret_cast<__half*>(smem + OFF_W1);
    __half* sW2 = reinterpret_cast<__half*>(smem + OFF_W2);
    float*  sC  = reinterpret_cast<float*>(smem + OFF_C);
    float*  sb1 = reinterpret_cast<float*>(smem + OFF_B1);
    const int tid  = threadIdx.x;
    const int wid  = tid >> 5;
    const int row0 = blockIdx.x * 128;

    // ---- stage b1 ----
    if (tid < 128) sb1[tid] = b1[tid];

    // ---- stage A (fp16 rows from g_axh), zero-pad past NN ----
    {
        int m = tid >> 1;              // 0..127
        int q = tid & 1;               // column half
        int r = row0 + m;
        const uint4* ar = reinterpret_cast<const uint4*>(
            g_axh + (size_t)(r < NN ? r : 0) * 128);
        uint4* dstp = reinterpret_cast<uint4*>(sA + m * LDA + q * 64);
        #pragma unroll
        for (int j = 0; j < 8; j++) {   // 8 x uint4 = 64 halves
            uint4 v = (r < NN) ? ar[q * 8 + j] : make_uint4(0u, 0u, 0u, 0u);
            dstp[j] = v;
        }
    }
    // ---- stage W1 [k][n] fp32 -> fp16 ----
    for (int idx = tid; idx < 128 * 64; idx += 256) {
        int k = idx >> 6;
        int n2 = (idx & 63) * 2;
        __half2 hh = __floats2half2_rn(W1[k * 128 + n2], W1[k * 128 + n2 + 1]);
        *reinterpret_cast<__half2*>(sW1 + k * LDA + n2) = hh;
    }
    // ---- stage W2 [k][n] fp32 -> fp16 ----
    for (int idx = tid; idx < 128 * 32; idx += 256) {
        int k = idx >> 5;
        int n2 = (idx & 31) * 2;
        __half2 hh = __floats2half2_rn(W2[k * 64 + n2], W2[k * 64 + n2 + 1]);
        *reinterpret_cast<__half2*>(sW2 + k * LDW2 + n2) = hh;
    }
    __syncthreads();

    // ---- GEMM1: C(128x128) = A @ W1 ; warp = 16-row strip ----
    {
        const int m0 = wid * 16;
        #pragma unroll
        for (int n0 = 0; n0 < 128; n0 += 16) {
            wmma::fragment<wmma::accumulator, 16, 16, 16, float> c;
            wmma::fill_fragment(c, 0.0f);
            #pragma unroll
            for (int k0 = 0; k0 < 128; k0 += 16) {
                wmma::fragment<wmma::matrix_a, 16, 16, 16, __half, wmma::row_major> a;
                wmma::fragment<wmma::matrix_b, 16, 16, 16, __half, wmma::row_major> b;
                wmma::load_matrix_sync(a, sA + m0 * LDA + k0, LDA);
                wmma::load_matrix_sync(b, sW1 + k0 * LDA + n0, LDA);
                wmma::mma_sync(c, a, b, c);
            }
            wmma::store_matrix_sync(sC + m0 * LDC + n0, c, LDC, wmma::mem_row_major);
        }
    }
    __syncthreads();

    // ---- epilogue1: H = relu(C + b1) * nout -> overwrite sA (fp16) ----
    for (int idx = tid; idx < 128 * 64; idx += 256) {
        int m = idx >> 6;
        int c2 = (idx & 63) * 2;
        int r = row0 + m;
        float no = (r < NN) ? g_nout[r] : 0.f;
        float v0 = fmaxf(sC[m * LDC + c2]     + sb1[c2],     0.f) * no;
        float v1 = fmaxf(sC[m * LDC + c2 + 1] + sb1[c2 + 1], 0.f) * no;
        *reinterpret_cast<__half2*>(sA + m * LDA + c2) = __floats2half2_rn(v0, v1);
    }
    __syncthreads();

    // ---- GEMM2: C2(128x64) = H @ W2 ----
    {
        const int m0 = wid * 16;
        #pragma unroll
        for (int n0 = 0; n0 < 64; n0 += 16) {
            wmma::fragment<wmma::accumulator, 16, 16, 16, float> c;
            wmma::fill_fragment(c, 0.0f);
            #pragma unroll
            for (int k0 = 0; k0 < 128; k0 += 16) {
                wmma::fragment<wmma::matrix_a, 16, 16, 16, __half, wmma::row_major> a;
                wmma::fragment<wmma::matrix_b, 16, 16, 16, __half, wmma::row_major> b;
                wmma::load_matrix_sync(a, sA + m0 * LDA + k0, LDA);
                wmma::load_matrix_sync(b, sW2 + k0 * LDW2 + n0, LDW2);
                wmma::mma_sync(c, a, b, c);
            }
            wmma::store_matrix_sync(sC + m0 * LDC + n0, c, LDC, wmma::mem_row_major);
        }
    }
    __syncthreads();

    // ---- epilogue2: y2 fp16 to gmem ----
    for (int idx = tid; idx < 128 * 32; idx += 256) {
        int m = idx >> 5;
        int c2 = (idx & 31) * 2;
        int r = row0 + m;
        if (r < NN) {
            __half2 hh = __floats2half2_rn(sC[m * LDC + c2], sC[m * LDC + c2 + 1]);
            *reinterpret_cast<__half2*>(g_y2h + (size_t)r * 64 + c2) = hh;
        }
    }
}

// ---------------- launch ------------------------------------------------------

extern "C" void kernel_launch(void* const* d_in, const int* in_sizes, int n_in,
                              void* d_out, int out_size) {
    const float* h  = (const float*)d_in[0];
    const float* W1 = (const float*)d_in[1];
    const float* b1 = (const float*)d_in[2];
    const float* W2 = (const float*)d_in[3];
    const float* b2 = (const float*)d_in[4];
    const int*   src = (const int*)d_in[5];
    const int*   dst = (const int*)d_in[6];
    float* out = (float*)d_out;
    (void)in_sizes; (void)n_in; (void)out_size;

    cudaFuncSetAttribute(fused_mlp_wmma,
                         cudaFuncAttributeMaxDynamicSharedMemorySize, WMMA_SMEM);

    void* odeg_p = nullptr; void* ideg_p = nullptr;
    cudaGetSymbolAddress(&odeg_p, g_odeg);
    cudaGetSymbolAddress(&ideg_p, g_ideg);
    cudaMemsetAsync(odeg_p, 0, NN * sizeof(int));
    cudaMemsetAsync(ideg_p, 0, NN * sizeof(int));

    degree_k<<<1024, 256>>>(src, dst);
    norm_partial_k<<<98, 512>>>();
    scanpart_k<<<1, SCAN_T>>>();
    h2half_k<<<1024, 256>>>(h);
    offsets_k<<<8, 128>>>();
    scatter_k<<<1024, 256>>>(src, dst);
    spmm1g_k<<<(NN * 32 + 255) / 256, 256>>>();              // 1 warp/node
    fused_mlp_wmma<<<(NN + 127) / 128, 256, WMMA_SMEM>>>(W1, b1, W2);
    spmm2g_k<<<(NN * 32 + 255) / 256, 256>>>(b2, out);       // 1 warp/node
}

// round 14
// speedup vs baseline: 1.7332x; 1.0019x over previous
#include <cuda_runtime.h>
#include <cuda_fp16.h>
#include <mma.h>
#include <cstdint>

using namespace nvcuda;

// Problem constants (fixed by the dataset)
static constexpr int NN = 50000;   // nodes
static constexpr int NE = 800000;  // edges (divisible by 4)
// features: 128 -> 128 (hidden) -> 64 (out)

// scan decomposition
static constexpr int SCAN_T = 1024;
static constexpr int CHUNK  = 52;          // 1024*52 = 53248 >= NN

// ---------------- scratch (__device__ globals; no allocs allowed) ------------
__device__ __half g_axh[(size_t)NN * 128]; // nin-scaled layer1 aggregate, fp16 (GEMM A)
__device__ __half g_y2h[(size_t)NN * 64];  // (relu(h1)*nout) @ W2, fp16
__device__ __half g_hx [(size_t)NN * 128]; // h * nout, fp16 (layer1 gather source)
__device__ int    g_odeg[NN];
__device__ int    g_ideg[NN];
__device__ float  g_nout[NN];
__device__ float  g_nin [NN];
__device__ int    g_off [NN + 1];
__device__ int    g_cur [NN];
__device__ int    g_bucket[NE];
__device__ int    g_part[SCAN_T];
__device__ int    g_pref[SCAN_T];

// ---------------- graph preprocessing ----------------------------------------

__global__ void degree_k(const int* __restrict__ src, const int* __restrict__ dst) {
    int i0 = blockIdx.x * blockDim.x + threadIdx.x;
    int stride = gridDim.x * blockDim.x;
    const int4* s4 = reinterpret_cast<const int4*>(src);
    const int4* d4 = reinterpret_cast<const int4*>(dst);
    for (int i = i0; i < NE / 4; i += stride) {
        int4 s = s4[i];
        int4 d = d4[i];
        atomicAdd(&g_odeg[s.x], 1);
        atomicAdd(&g_odeg[s.y], 1);
        atomicAdd(&g_odeg[s.z], 1);
        atomicAdd(&g_odeg[s.w], 1);
        atomicAdd(&g_ideg[d.x], 1);
        atomicAdd(&g_ideg[d.y], 1);
        atomicAdd(&g_ideg[d.z], 1);
        atomicAdd(&g_ideg[d.w], 1);
    }
}

__global__ void norm_partial_k() {
    int gid = blockIdx.x * blockDim.x + threadIdx.x;
    int stride = gridDim.x * blockDim.x;
    for (int i = gid; i < NN; i += stride) {
        int od = g_odeg[i]; if (od < 1) od = 1;
        int id = g_ideg[i]; if (id < 1) id = 1;
        g_nout[i] = rsqrtf((float)od);
        g_nin[i]  = rsqrtf((float)id);
    }
    if (gid < SCAN_T) {
        int begin = gid * CHUNK;
        int endi  = begin + CHUNK; if (endi > NN) endi = NN;
        int sum = 0;
        if (begin < NN) {
            const int4* p = reinterpret_cast<const int4*>(g_ideg);
            #pragma unroll 13
            for (int i = begin / 4; i < endi / 4; i++) {
                int4 v = p[i];
                sum += v.x + v.y + v.z + v.w;
            }
        }
        g_part[gid] = sum;
    }
}

__global__ void __launch_bounds__(SCAN_T, 1) scanpart_k() {
    __shared__ int wsum[32];
    int t    = threadIdx.x;
    int lane = t & 31;
    int wid  = t >> 5;

    int own = g_part[t];
    int v = own;
    #pragma unroll
    for (int d = 1; d < 32; d <<= 1) {
        int n = __shfl_up_sync(0xffffffffu, v, d);
        if (lane >= d) v += n;
    }
    if (lane == 31) wsum[wid] = v;
    __syncthreads();
    if (wid == 0) {
        int w = wsum[lane];
        #pragma unroll
        for (int d = 1; d < 32; d <<= 1) {
            int n = __shfl_up_sync(0xffffffffu, w, d);
            if (lane >= d) w += n;
        }
        wsum[lane] = w;
    }
    __syncthreads();

    g_pref[t] = v - own + (wid > 0 ? wsum[wid - 1] : 0);
}

__global__ void offsets_k() {
    int t = blockIdx.x * blockDim.x + threadIdx.x;
    if (t >= SCAN_T) return;
    int begin = t * CHUNK;
    int endi  = begin + CHUNK; if (endi > NN) endi = NN;
    int running = g_pref[t];
    for (int i = begin; i < endi; i++) {
        g_off[i] = running;
        g_cur[i] = running;
        running += g_ideg[i];
    }
    if (t == SCAN_T - 1) g_off[NN] = NE;
}

__global__ void scatter_k(const int* __restrict__ src, const int* __restrict__ dst) {
    int i0 = blockIdx.x * blockDim.x + threadIdx.x;
    int stride = gridDim.x * blockDim.x;
    const int4* s4 = reinterpret_cast<const int4*>(src);
    const int4* d4 = reinterpret_cast<const int4*>(dst);
    for (int i = i0; i < NE / 4; i += stride) {
        int4 s = s4[i];
        int4 d = d4[i];
        g_bucket[atomicAdd(&g_cur[d.x], 1)] = s.x;
        g_bucket[atomicAdd(&g_cur[d.y], 1)] = s.y;
        g_bucket[atomicAdd(&g_cur[d.z], 1)] = s.z;
        g_bucket[atomicAdd(&g_cur[d.w], 1)] = s.w;
    }
}

// ---------------- fp16 pre-scaled features ------------------------------------
__global__ void h2half_k(const float* __restrict__ h) {
    int i0 = blockIdx.x * blockDim.x + threadIdx.x;
    int stride = gridDim.x * blockDim.x;
    const float4* h4 = reinterpret_cast<const float4*>(h);
    uint2* o = reinterpret_cast<uint2*>(g_hx);
    for (int i = i0; i < NN * 32; i += stride) {
        int row = i >> 5;
        float s = g_nout[row];
        float4 v = h4[i];
        __half2 a = __floats2half2_rn(v.x * s, v.y * s);
        __half2 b = __floats2half2_rn(v.z * s, v.w * s);
        uint2 pkd;
        pkd.x = *reinterpret_cast<unsigned*>(&a);
        pkd.y = *reinterpret_cast<unsigned*>(&b);
        o[i] = pkd;
    }
}

// ---------------- layer-1 SpMM as fp16 gather -> fp16 A ------------------------
// 4-deep unrolled: 4 independent row gathers in flight (MLP=4).
__global__ void spmm1g_k() {
    unsigned w = (blockIdx.x * blockDim.x + threadIdx.x) >> 5;
    if (w >= NN) return;
    int lane = threadIdx.x & 31;
    int beg = g_off[w];
    int end = g_off[w + 1];
    const uint2* hx = reinterpret_cast<const uint2*>(g_hx);

    float4 acc = make_float4(0.f, 0.f, 0.f, 0.f);
    int e = beg;
    for (; e + 3 < end; e += 4) {
        int s0 = __ldg(&g_bucket[e]);
        int s1 = __ldg(&g_bucket[e + 1]);
        int s2 = __ldg(&g_bucket[e + 2]);
        int s3 = __ldg(&g_bucket[e + 3]);
        uint2 p0 = hx[(size_t)s0 * 32 + lane];
        uint2 p1 = hx[(size_t)s1 * 32 + lane];
        uint2 p2 = hx[(size_t)s2 * 32 + lane];
        uint2 p3 = hx[(size_t)s3 * 32 + lane];
        float2 a0 = __half22float2(*reinterpret_cast<__half2*>(&p0.x));
        float2 b0 = __half22float2(*reinterpret_cast<__half2*>(&p0.y));
        float2 a1 = __half22float2(*reinterpret_cast<__half2*>(&p1.x));
        float2 b1 = __half22float2(*reinterpret_cast<__half2*>(&p1.y));
        float2 a2 = __half22float2(*reinterpret_cast<__half2*>(&p2.x));
        float2 b2 = __half22float2(*reinterpret_cast<__half2*>(&p2.y));
        float2 a3 = __half22float2(*reinterpret_cast<__half2*>(&p3.x));
        float2 b3 = __half22float2(*reinterpret_cast<__half2*>(&p3.y));
        acc.x += (a0.x + a1.x) + (a2.x + a3.x);
        acc.y += (a0.y + a1.y) + (a2.y + a3.y);
        acc.z += (b0.x + b1.x) + (b2.x + b3.x);
        acc.w += (b0.y + b1.y) + (b2.y + b3.y);
    }
    for (; e < end; e++) {
        int s0 = __ldg(&g_bucket[e]);
        uint2 p0 = hx[(size_t)s0 * 32 + lane];
        float2 a0 = __half22float2(*reinterpret_cast<__half2*>(&p0.x));
        float2 b0 = __half22float2(*reinterpret_cast<__half2*>(&p0.y));
        acc.x += a0.x;  acc.y += a0.y;
        acc.z += b0.x;  acc.w += b0.y;
    }
    float ni = g_nin[w];
    __half2 h0 = __floats2half2_rn(acc.x * ni, acc.y * ni);
    __half2 h1 = __floats2half2_rn(acc.z * ni, acc.w * ni);
    uint2 pkd;
    pkd.x = *reinterpret_cast<unsigned*>(&h0);
    pkd.y = *reinterpret_cast<unsigned*>(&h1);
    reinterpret_cast<uint2*>(g_axh)[(size_t)w * 32 + lane] = pkd;
}

// ---------------- layer-2 SpMM as fp16 gather + fused epilogue -----------------
__global__ void spmm2g_k(const float* __restrict__ b2, float* __restrict__ out) {
    unsigned w = (blockIdx.x * blockDim.x + threadIdx.x) >> 5;
    if (w >= NN) return;
    int lane = threadIdx.x & 31;
    int beg = g_off[w];
    int end = g_off[w + 1];
    const unsigned* y2 = reinterpret_cast<const unsigned*>(g_y2h);

    float2 acc = make_float2(0.f, 0.f);
    int e = beg;
    for (; e + 3 < end; e += 4) {
        int s0 = __ldg(&g_bucket[e]);
        int s1 = __ldg(&g_bucket[e + 1]);
        int s2 = __ldg(&g_bucket[e + 2]);
        int s3 = __ldg(&g_bucket[e + 3]);
        unsigned p0 = y2[(size_t)s0 * 32 + lane];
        unsigned p1 = y2[(size_t)s1 * 32 + lane];
        unsigned p2 = y2[(size_t)s2 * 32 + lane];
        unsigned p3 = y2[(size_t)s3 * 32 + lane];
        float2 v0 = __half22float2(*reinterpret_cast<__half2*>(&p0));
        float2 v1 = __half22float2(*reinterpret_cast<__half2*>(&p1));
        float2 v2 = __half22float2(*reinterpret_cast<__half2*>(&p2));
        float2 v3 = __half22float2(*reinterpret_cast<__half2*>(&p3));
        acc.x += (v0.x + v1.x) + (v2.x + v3.x);
        acc.y += (v0.y + v1.y) + (v2.y + v3.y);
    }
    for (; e < end; e++) {
        int s0 = __ldg(&g_bucket[e]);
        unsigned p0 = y2[(size_t)s0 * 32 + lane];
        float2 v0 = __half22float2(*reinterpret_cast<__half2*>(&p0));
        acc.x += v0.x;
        acc.y += v0.y;
    }
    float ni = g_nin[w];
    float2 bb = reinterpret_cast<const float2*>(b2)[lane];
    float2 o;
    o.x = fmaxf(fmaf(acc.x, ni, bb.x), 0.f);
    o.y = fmaxf(fmaf(acc.y, ni, bb.y), 0.f);
    reinterpret_cast<float2*>(out)[(size_t)w * 32 + lane] = o;
}

// ================= wmma (HMMA) fused double-GEMM ==============================
static constexpr int LDA  = 136;   // halves, padded
static constexpr int LDW2 = 72;    // halves
static constexpr int LDC  = 132;   // floats

static constexpr int OFF_A  = 0;
static constexpr int OFF_W1 = OFF_A  + 128 * LDA * 2;
static constexpr int OFF_W2 = OFF_W1 + 128 * LDA * 2;
static constexpr int OFF_C  = OFF_W2 + 128 * LDW2 * 2;
static constexpr int OFF_B1 = OFF_C  + 128 * LDC * 4;
static constexpr int WMMA_SMEM = OFF_B1 + 512;

__global__ void __launch_bounds__(256, 1)
fused_mlp_wmma(const float* __restrict__ W1, const float* __restrict__ b1,
               const float* __restrict__ W2) {
    extern __shared__ char smem[];
    __half* sA  = reinterpret_cast<__half*>(smem + OFF_A);
    __half* sW1 = reinterpret_cast<__half*>(smem + OFF_W1);
    __half* sW2 = reinterpret_cast<__half*>(smem + OFF_W2);
    float*  sC  = reinterpret_cast<float*>(smem + OFF_C);
    float*  sb1 = reinterpret_cast<float*>(smem + OFF_B1);
    const int tid  = threadIdx.x;
    const int wid  = tid >> 5;
    const int row0 = blockIdx.x * 128;

    if (tid < 128) sb1[tid] = b1[tid];

    {
        int m = tid >> 1;
        int q = tid & 1;
        int r = row0 + m;
        const uint4* ar = reinterpret_cast<const uint4*>(
            g_axh + (size_t)(r < NN ? r : 0) * 128);
        uint4* dstp = reinterpret_cast<uint4*>(sA + m * LDA + q * 64);
        #pragma unroll
        for (int j = 0; j < 8; j++) {
            uint4 v = (r < NN) ? ar[q * 8 + j] : make_uint4(0u, 0u, 0u, 0u);
            dstp[j] = v;
        }
    }
    for (int idx = tid; idx < 128 * 64; idx += 256) {
        int k = idx >> 6;
        int n2 = (idx & 63) * 2;
        __half2 hh = __floats2half2_rn(W1[k * 128 + n2], W1[k * 128 + n2 + 1]);
        *reinterpret_cast<__half2*>(sW1 + k * LDA + n2) = hh;
    }
    for (int idx = tid; idx < 128 * 32; idx += 256) {
        int k = idx >> 5;
        int n2 = (idx & 31) * 2;
        __half2 hh = __floats2half2_rn(W2[k * 64 + n2], W2[k * 64 + n2 + 1]);
        *reinterpret_cast<__half2*>(sW2 + k * LDW2 + n2) = hh;
    }
    __syncthreads();

    {
        const int m0 = wid * 16;
        #pragma unroll
        for (int n0 = 0; n0 < 128; n0 += 16) {
            wmma::fragment<wmma::accumulator, 16, 16, 16, float> c;
            wmma::fill_fragment(c, 0.0f);
            #pragma unroll
            for (int k0 = 0; k0 < 128; k0 += 16) {
                wmma::fragment<wmma::matrix_a, 16, 16, 16, __half, wmma::row_major> a;
                wmma::fragment<wmma::matrix_b, 16, 16, 16, __half, wmma::row_major> b;
                wmma::load_matrix_sync(a, sA + m0 * LDA + k0, LDA);
                wmma::load_matrix_sync(b, sW1 + k0 * LDA + n0, LDA);
                wmma::mma_sync(c, a, b, c);
            }
            wmma::store_matrix_sync(sC + m0 * LDC + n0, c, LDC, wmma::mem_row_major);
        }
    }
    __syncthreads();

    for (int idx = tid; idx < 128 * 64; idx += 256) {
        int m = idx >> 6;
        int c2 = (idx & 63) * 2;
        int r = row0 + m;
        float no = (r < NN) ? g_nout[r] : 0.f;
        float v0 = fmaxf(sC[m * LDC + c2]     + sb1[c2],     0.f) * no;
        float v1 = fmaxf(sC[m * LDC + c2 + 1] + sb1[c2 + 1], 0.f) * no;
        *reinterpret_cast<__half2*>(sA + m * LDA + c2) = __floats2half2_rn(v0, v1);
    }
    __syncthreads();

    {
        const int m0 = wid * 16;
        #pragma unroll
        for (int n0 = 0; n0 < 64; n0 += 16) {
            wmma::fragment<wmma::accumulator, 16, 16, 16, float> c;
            wmma::fill_fragment(c, 0.0f);
            #pragma unroll
            for (int k0 = 0; k0 < 128; k0 += 16) {
                wmma::fragment<wmma::matrix_a, 16, 16, 16, __half, wmma::row_major> a;
                wmma::fragment<wmma::matrix_b, 16, 16, 16, __half, wmma::row_major> b;
                wmma::load_matrix_sync(a, sA + m0 * LDA + k0, LDA);
                wmma::load_matrix_sync(b, sW2 + k0 * LDW2 + n0, LDW2);
                wmma::mma_sync(c, a, b, c);
            }
            wmma::store_matrix_sync(sC + m0 * LDC + n0, c, LDC, wmma::mem_row_major);
        }
    }
    __syncthreads();

    for (int idx = tid; idx < 128 * 32; idx += 256) {
        int m = idx >> 5;
        int c2 = (idx & 31) * 2;
        int r = row0 + m;
        if (r < NN) {
            __half2 hh = __floats2half2_rn(sC[m * LDC + c2], sC[m * LDC + c2 + 1]);
            *reinterpret_cast<__half2*>(g_y2h + (size_t)r * 64 + c2) = hh;
        }
    }
}

// ---------------- launch ------------------------------------------------------

extern "C" void kernel_launch(void* const* d_in, const int* in_sizes, int n_in,
                              void* d_out, int out_size) {
    const float* h  = (const float*)d_in[0];
    const float* W1 = (const float*)d_in[1];
    const float* b1 = (const float*)d_in[2];
    const float* W2 = (const float*)d_in[3];
    const float* b2 = (const float*)d_in[4];
    const int*   src = (const int*)d_in[5];
    const int*   dst = (const int*)d_in[6];
    float* out = (float*)d_out;
    (void)in_sizes; (void)n_in; (void)out_size;

    cudaFuncSetAttribute(fused_mlp_wmma,
                         cudaFuncAttributeMaxDynamicSharedMemorySize, WMMA_SMEM);

    // side stream + events for overlapping h2half with the CSR build
    static cudaStream_t s2 = nullptr;
    static cudaEvent_t evFork = nullptr, evJoin = nullptr;
    if (s2 == nullptr) {
        cudaStreamCreateWithFlags(&s2, cudaStreamNonBlocking);
        cudaEventCreateWithFlags(&evFork, cudaEventDisableTiming);
        cudaEventCreateWithFlags(&evJoin, cudaEventDisableTiming);
    }

    void* odeg_p = nullptr; void* ideg_p = nullptr;
    cudaGetSymbolAddress(&odeg_p, g_odeg);
    cudaGetSymbolAddress(&ideg_p, g_ideg);
    cudaMemsetAsync(odeg_p, 0, NN * sizeof(int));
    cudaMemsetAsync(ideg_p, 0, NN * sizeof(int));

    degree_k<<<512, 256>>>(src, dst);
    norm_partial_k<<<98, 512>>>();

    // fork: h2half depends only on norms; overlap with scan/offsets/scatter
    cudaEventRecord(evFork, 0);
    cudaStreamWaitEvent(s2, evFork, 0);
    h2half_k<<<1024, 256, 0, s2>>>(h);
    cudaEventRecord(evJoin, s2);

    scanpart_k<<<1, SCAN_T>>>();
    offsets_k<<<8, 128>>>();
    scatter_k<<<512, 256>>>(src, dst);

    cudaStreamWaitEvent(0, evJoin, 0);   // join before the gather reads g_hx

    spmm1g_k<<<(NN * 32 + 255) / 256, 256>>>();              // 1 warp/node
    fused_mlp_wmma<<<(NN + 127) / 128, 256, WMMA_SMEM>>>(W1, b1, W2);
    spmm2g_k<<<(NN * 32 + 255) / 256, 256>>>(b2, out);       // 1 warp/node
}